// round 4
// baseline (speedup 1.0000x reference)
#include <cuda_runtime.h>
#include <math.h>

// Problem constants (fixed by the dataset)
#define B_DIM 512
#define F_DIM 512
#define H_DIM 512
#define E_DIM 8

// GEMM tiling: 128x128 CTA tile, 8x8 micro-tile, 256 threads, split-K=8
#define TM 128
#define TN 128
#define TK 16
#define LSTR 132         // smem row stride (floats): 132*4=528B, 16B-aligned rows
#define NTHREADS 256
#define SPLITK 8

// -------- scratch (no allocations allowed; __device__ globals) --------
__device__ float d_P[SPLITK * B_DIM * H_DIM];   // split-K partials (8 MB)
__device__ float d_G0[B_DIM * H_DIM];
__device__ float d_G1[B_DIM * H_DIM];
__device__ float d_gate[B_DIM * E_DIM];
__device__ float d_H1[B_DIM * H_DIM];
__device__ float d_H2[B_DIM * H_DIM];

__device__ __forceinline__ float elu_f(float x) {
    return x > 0.0f ? x : expm1f(x);
}

// B-smem swizzle: permute 16-byte groups within a k-row so that the 16
// b-fragment LDS.128s of a warp spread across all 32 banks (removes the
// 4-way conflict of the naive tx*8 pattern). Self-inverse; applied at both
// store (stage) and load (compute). 'g' = float4-group index 0..31, 'krow'
// = k-row 0..15.
__device__ __forceinline__ int bswz(int krow, int g) {
    return g ^ ((krow & 3) << 2);
}

// ----------------------------------------------------------------------
// gemm_part: split-K partial of C = A' @ B'^T
//   GATED==0: A' = A [M,K] row-major, B'(n,k) = Bm[n*K + k]   (x @ W^T)
//   GATED==1: A'(m,k) = gate[m, k>>9] * A[m, k&511]   (A is [M,512])
//             B'(n,k) = alpha[(k>>9)*N*512 + n*512 + (k&511)]
// Grid: (M/TM, N/TN, SPLITK). z computes k in [z*NT*TK, (z+1)*NT*TK).
// ----------------------------------------------------------------------
template <int GATED, int NT>
__global__ __launch_bounds__(NTHREADS)
void gemm_part(const float* __restrict__ A,
               const float* __restrict__ Bm,
               const float* __restrict__ gate,
               float* __restrict__ P,
               int K)
{
    __shared__ __align__(16) float As[2][TK][LSTR];
    __shared__ __align__(16) float Bs[2][TK][TN];   // swizzled; TN=128 floats/row

    const int tid = threadIdx.x;
    const int tx  = tid & 15;          // 16 n-groups of 8
    const int ty  = tid >> 4;          // 16 m-groups of 8
    const int bm  = blockIdx.x * TM;
    const int bn  = blockIdx.y * TN;
    const int z   = blockIdx.z;
    const int k0  = z * NT * TK;

    // loader mapping: 128 rows x 16 k; each thread loads one row's 8 k-floats
    const int lrow = tid >> 1;         // 0..127
    const int lk   = (tid & 1) * 8;    // 0 or 8

    // GATED: hoist the 8 gate scalars for this thread's fixed A-row
    float gs[E_DIM];
    if (GATED) {
#pragma unroll
        for (int e = 0; e < E_DIM; ++e)
            gs[e] = __ldg(gate + (bm + lrow) * E_DIM + e);
    }

    float acc[8][8];
#pragma unroll
    for (int i = 0; i < 8; ++i)
#pragma unroll
        for (int j = 0; j < 8; ++j) acc[i][j] = 0.0f;

    float4 a0, a1, b0, b1;   // staged global loads (8 k-floats each of A,B)

    auto loadAB = [&](int kt) {
        const int kg = k0 + kt * TK + lk;   // 8-aligned; never crosses 512-boundary
        if (GATED) {
            const int e = kg >> 9;
            const int f = kg & 511;
            const float* ap = A + (bm + lrow) * F_DIM + f;
            a0 = *(const float4*)(ap);
            a1 = *(const float4*)(ap + 4);
            const float g = gs[e];
            a0.x *= g; a0.y *= g; a0.z *= g; a0.w *= g;
            a1.x *= g; a1.y *= g; a1.z *= g; a1.w *= g;
            const float* bp = Bm + ((size_t)e * H_DIM + (bn + lrow)) * F_DIM + f;
            b0 = *(const float4*)(bp);
            b1 = *(const float4*)(bp + 4);
        } else {
            const float* ap = A + (bm + lrow) * K + kg;
            a0 = *(const float4*)(ap);
            a1 = *(const float4*)(ap + 4);
            const float* bp = Bm + (bn + lrow) * K + kg;
            b0 = *(const float4*)(bp);
            b1 = *(const float4*)(bp + 4);
        }
    };

    auto stage = [&](int buf) {
        // A: [k][m] transposed scalar stores (unchanged)
        As[buf][lk + 0][lrow] = a0.x;
        As[buf][lk + 1][lrow] = a0.y;
        As[buf][lk + 2][lrow] = a0.z;
        As[buf][lk + 3][lrow] = a0.w;
        As[buf][lk + 4][lrow] = a1.x;
        As[buf][lk + 5][lrow] = a1.y;
        As[buf][lk + 6][lrow] = a1.z;
        As[buf][lk + 7][lrow] = a1.w;
        // B: [k][n] with XOR-swizzled float4 groups. This thread owns B-row
        // (bn+lrow), k-values lk..lk+7. Element (krow, n=lrow) lives in
        // group g0 = lrow>>2, lane lrow&3, at swizzled group bswz(krow,g0).
        const int g0 = lrow >> 2;
        const int li = lrow & 3;
        const float bk[8] = {b0.x, b0.y, b0.z, b0.w, b1.x, b1.y, b1.z, b1.w};
#pragma unroll
        for (int j = 0; j < 8; ++j) {
            const int krow = lk + j;
            Bs[buf][krow][bswz(krow, g0) * 4 + li] = bk[j];
        }
    };

    loadAB(0);
    stage(0);
    __syncthreads();

#pragma unroll 1
    for (int t = 0; t < NT; ++t) {
        const int buf = t & 1;
        const bool more = (t + 1) < NT;
        if (more) loadAB(t + 1);

#pragma unroll
        for (int k = 0; k < TK; ++k) {
            const float4 av0 = *(const float4*)&As[buf][k][ty * 8];
            const float4 av1 = *(const float4*)&As[buf][k][ty * 8 + 4];
            // b-frag groups for this thread: logical groups 2*tx, 2*tx+1
            const float4 bv0 = *(const float4*)&Bs[buf][k][bswz(k, 2 * tx) * 4];
            const float4 bv1 = *(const float4*)&Bs[buf][k][bswz(k, 2 * tx + 1) * 4];
            const float a8[8] = {av0.x, av0.y, av0.z, av0.w, av1.x, av1.y, av1.z, av1.w};
            const float b8[8] = {bv0.x, bv0.y, bv0.z, bv0.w, bv1.x, bv1.y, bv1.z, bv1.w};
#pragma unroll
            for (int i = 0; i < 8; ++i)
#pragma unroll
                for (int j = 0; j < 8; ++j)
                    acc[i][j] = fmaf(a8[i], b8[j], acc[i][j]);
        }

        if (more) stage(buf ^ 1);
        __syncthreads();
    }

    float* Cp = P + (size_t)z * B_DIM * H_DIM;
#pragma unroll
    for (int i = 0; i < 8; ++i) {
        float* row = Cp + (size_t)(bm + ty * 8 + i) * H_DIM + bn + tx * 8;
        *(float4*)(row)     = make_float4(acc[i][0], acc[i][1], acc[i][2], acc[i][3]);
        *(float4*)(row + 4) = make_float4(acc[i][4], acc[i][5], acc[i][6], acc[i][7]);
    }
}

// ----------------------------------------------------------------------
// combine 8 partials + broadcast bias (+ optional elu):  gating layers
// ----------------------------------------------------------------------
__global__ __launch_bounds__(256)
void combine_bias(const float* __restrict__ P, const float* __restrict__ bias,
                  float* __restrict__ out, int do_elu)
{
    const int i = blockIdx.x * blockDim.x + threadIdx.x;  // one float4
    const int base = i * 4;
    const int n = base & (H_DIM - 1);
    float4 s = *(const float4*)(P + base);
#pragma unroll
    for (int zz = 1; zz < SPLITK; ++zz) {
        float4 p = *(const float4*)(P + (size_t)zz * B_DIM * H_DIM + base);
        s.x += p.x; s.y += p.y; s.z += p.z; s.w += p.w;
    }
    float4 bv = *(const float4*)(bias + n);
    float v0 = s.x + bv.x, v1 = s.y + bv.y, v2 = s.z + bv.z, v3 = s.w + bv.w;
    if (do_elu) { v0 = elu_f(v0); v1 = elu_f(v1); v2 = elu_f(v2); v3 = elu_f(v3); }
    *(float4*)(out + base) = make_float4(v0, v1, v2, v3);
}

// ----------------------------------------------------------------------
// combine 8 partials + blended expert bias (+ optional elu):  MoE layers
//   bias[m,n] = sum_e gate[m,e] * beta[e*512 + n]
// ----------------------------------------------------------------------
__global__ __launch_bounds__(256)
void combine_moe(const float* __restrict__ P, const float* __restrict__ gate,
                 const float* __restrict__ beta, float* __restrict__ out, int do_elu)
{
    const int i = blockIdx.x * blockDim.x + threadIdx.x;  // one float4
    const int base = i * 4;
    const int m = base >> 9;          // /512
    const int n = base & 511;
    float4 s = *(const float4*)(P + base);
#pragma unroll
    for (int zz = 1; zz < SPLITK; ++zz) {
        float4 p = *(const float4*)(P + (size_t)zz * B_DIM * H_DIM + base);
        s.x += p.x; s.y += p.y; s.z += p.z; s.w += p.w;
    }
#pragma unroll
    for (int e = 0; e < E_DIM; ++e) {
        const float ge = __ldg(gate + m * E_DIM + e);
        const float4 bb = *(const float4*)(beta + e * H_DIM + n);
        s.x = fmaf(ge, bb.x, s.x);
        s.y = fmaf(ge, bb.y, s.y);
        s.z = fmaf(ge, bb.z, s.z);
        s.w = fmaf(ge, bb.w, s.w);
    }
    float v0 = s.x, v1 = s.y, v2 = s.z, v3 = s.w;
    if (do_elu) { v0 = elu_f(v0); v1 = elu_f(v1); v2 = elu_f(v2); v3 = elu_f(v3); }
    *(float4*)(out + base) = make_float4(v0, v1, v2, v3);
}

// ----------------------------------------------------------------------
// final gating layer: logits = G1 @ gw2^T + gb2  (N=8, K=512), row softmax
// one warp per batch row
// ----------------------------------------------------------------------
__global__ __launch_bounds__(256)
void gating_softmax(const float* __restrict__ G, const float* __restrict__ W,
                    const float* __restrict__ bias, float* __restrict__ gate)
{
    const int warp = (blockIdx.x * blockDim.x + threadIdx.x) >> 5;
    const int lane = threadIdx.x & 31;
    if (warp >= B_DIM) return;

    float acc[E_DIM] = {0, 0, 0, 0, 0, 0, 0, 0};
    const float* grow = G + (size_t)warp * H_DIM;
    for (int k = lane; k < H_DIM; k += 32) {
        const float xv = grow[k];
#pragma unroll
        for (int e = 0; e < E_DIM; ++e)
            acc[e] = fmaf(xv, __ldg(W + e * H_DIM + k), acc[e]);
    }
#pragma unroll
    for (int e = 0; e < E_DIM; ++e) {
#pragma unroll
        for (int off = 16; off > 0; off >>= 1)
            acc[e] += __shfl_xor_sync(0xffffffffu, acc[e], off);
    }
    if (lane == 0) {
        float v[E_DIM], mx = -1e30f;
#pragma unroll
        for (int e = 0; e < E_DIM; ++e) {
            v[e] = acc[e] + __ldg(bias + e);
            mx = fmaxf(mx, v[e]);
        }
        float s = 0.f;
#pragma unroll
        for (int e = 0; e < E_DIM; ++e) { v[e] = expf(v[e] - mx); s += v[e]; }
        const float inv = 1.0f / s;
#pragma unroll
        for (int e = 0; e < E_DIM; ++e)
            gate[warp * E_DIM + e] = v[e] * inv;
    }
}

// ----------------------------------------------------------------------
extern "C" void kernel_launch(void* const* d_in, const int* in_sizes, int n_in,
                              void* d_out, int out_size)
{
    const float* x      = (const float*)d_in[0];
    const float* gw0    = (const float*)d_in[1];
    const float* gb0    = (const float*)d_in[2];
    const float* gw1    = (const float*)d_in[3];
    const float* gb1    = (const float*)d_in[4];
    const float* gw2    = (const float*)d_in[5];
    const float* gb2    = (const float*)d_in[6];
    const float* alpha0 = (const float*)d_in[7];
    const float* beta0  = (const float*)d_in[8];
    const float* alpha1 = (const float*)d_in[9];
    const float* beta1  = (const float*)d_in[10];
    const float* alpha2 = (const float*)d_in[11];
    const float* beta2  = (const float*)d_in[12];
    float* out = (float*)d_out;

    float *P, *G0, *G1, *gate, *H1, *H2;
    cudaGetSymbolAddress((void**)&P,    d_P);
    cudaGetSymbolAddress((void**)&G0,   d_G0);
    cudaGetSymbolAddress((void**)&G1,   d_G1);
    cudaGetSymbolAddress((void**)&gate, d_gate);
    cudaGetSymbolAddress((void**)&H1,   d_H1);
    cudaGetSymbolAddress((void**)&H2,   d_H2);

    const dim3 gg(B_DIM / TM, H_DIM / TN, SPLITK);  // 4 x 4 x 8 = 128 CTAs
    const int cgrid = (B_DIM * H_DIM / 4) / 256;    // 256 blocks

    // k-tiles per split: gating K=512/8 -> 64 -> NT=4; expert K=4096/8 -> 512 -> NT=32
    constexpr int NT_GATE   = (F_DIM / SPLITK) / TK;          // 4
    constexpr int NT_EXPERT = (E_DIM * F_DIM / SPLITK) / TK;  // 32

    // gating MLP
    gemm_part<0, NT_GATE><<<gg, NTHREADS>>>(x,  gw0, nullptr, P, F_DIM);
    combine_bias<<<cgrid, 256>>>(P, gb0, G0, 1);
    gemm_part<0, NT_GATE><<<gg, NTHREADS>>>(G0, gw1, nullptr, P, H_DIM);
    combine_bias<<<cgrid, 256>>>(P, gb1, G1, 1);
    gating_softmax<<<(B_DIM * 32) / 256, 256>>>(G1, gw2, gb2, gate);

    // expert layer 1: K = E*F = 4096
    gemm_part<1, NT_EXPERT><<<gg, NTHREADS>>>(x,  alpha0, gate, P, E_DIM * F_DIM);
    combine_moe<<<cgrid, 256>>>(P, gate, beta0, H1, 1);
    // expert layer 2
    gemm_part<1, NT_EXPERT><<<gg, NTHREADS>>>(H1, alpha1, gate, P, E_DIM * H_DIM);
    combine_moe<<<cgrid, 256>>>(P, gate, beta1, H2, 1);
    // expert layer 3 (no activation) -> output
    gemm_part<1, NT_EXPERT><<<gg, NTHREADS>>>(H2, alpha2, gate, P, E_DIM * H_DIM);
    combine_moe<<<cgrid, 256>>>(P, gate, beta2, out, 0);
}

// round 14
// speedup vs baseline: 1.4831x; 1.4831x over previous
#include <cuda_runtime.h>
#include <cuda_fp16.h>
#include <cstdint>
#include <cstddef>
#include <math.h>

// Problem constants (fixed by the dataset)
#define B_DIM 512
#define F_DIM 512
#define H_DIM 512
#define E_DIM 8
#define SPLITK 8

#define NTHREADS 256
#define TILE_M 128
#define TILE_N 128
#define KCH 64            // fp16 k-elements staged per chunk
#define ASTR 72           // smem row stride in halves (144B = 9*16B -> conflict-free ldmatrix)

// -------- scratch (no allocations allowed; __device__ globals) --------
__device__ float d_P[SPLITK * B_DIM * H_DIM];   // split-K partials
__device__ float d_G0[B_DIM * H_DIM];
__device__ float d_G1[B_DIM * H_DIM];
__device__ float d_gate[B_DIM * E_DIM];
__device__ float d_H1[B_DIM * H_DIM];
__device__ float d_H2[B_DIM * H_DIM];

__device__ __forceinline__ float elu_f(float x) { return x > 0.0f ? x : expm1f(x); }

__device__ __forceinline__ uint32_t smem_u32(const void* p) {
    uint32_t a;
    asm("{ .reg .u64 t; cvta.to.shared.u64 t, %1; cvt.u32.u64 %0, t; }"
        : "=r"(a) : "l"(p));
    return a;
}

// ldmatrix x4: four 8x8 b16 matrices (sm_75+, no arch suffix needed)
__device__ __forceinline__ void ldm_x4(uint32_t& r0, uint32_t& r1,
                                       uint32_t& r2, uint32_t& r3, uint32_t addr) {
    asm volatile("ldmatrix.sync.aligned.m8n8.x4.shared.b16 {%0,%1,%2,%3}, [%4];"
                 : "=r"(r0), "=r"(r1), "=r"(r2), "=r"(r3) : "r"(addr));
}

// warp-level HMMA: m16n8k16, fp16 in, fp32 accumulate (sm_80+)
__device__ __forceinline__ void mma16816(float* c,
                                         uint32_t a0, uint32_t a1, uint32_t a2, uint32_t a3,
                                         uint32_t b0, uint32_t b1) {
    asm volatile(
        "mma.sync.aligned.m16n8k16.row.col.f32.f16.f16.f32 "
        "{%0,%1,%2,%3}, {%4,%5,%6,%7}, {%8,%9}, {%0,%1,%2,%3};"
        : "+f"(c[0]), "+f"(c[1]), "+f"(c[2]), "+f"(c[3])
        : "r"(a0), "r"(a1), "r"(a2), "r"(a3), "r"(b0), "r"(b1));
}

// ----------------------------------------------------------------------
// hmma_gemm: split-K partial of C = A' @ B'^T (fp16 tensor cores, fp32 acc)
//   GATED==0: A'(m,k)=A[m*K+k], B'(n,k)=Bm[n*K+k];  this CTA's k-window is
//             [z*NCHUNK*KCH, ...).
//   GATED==1: K = E*512 and each z-slice is exactly one expert (e == z):
//             A'(m,k)=gate[m,z]*A[m*512+f], B'(n,k)=alpha[(z*512+n)*512+f]
// Grid (4,4,SPLITK); CTA tile 128x128; 8 warps, warp tile 64x32.
// Staging is software-pipelined: chunk c+1's global loads are issued into
// registers before chunk c's MMA phase, hiding LDG latency behind compute.
// ----------------------------------------------------------------------
template <int GATED, int NCHUNK>
__global__ __launch_bounds__(NTHREADS)
void hmma_gemm(const float* __restrict__ A, const float* __restrict__ Bm,
               const float* __restrict__ gate, float* __restrict__ P, int K)
{
    __shared__ __align__(16) __half As[TILE_M][ASTR];
    __shared__ __align__(16) __half Bs[TILE_N][ASTR];

    const int tid  = threadIdx.x;
    const int wid  = tid >> 5;
    const int lane = tid & 31;
    const int bm = blockIdx.x * TILE_M;
    const int bn = blockIdx.y * TILE_N;
    const int z  = blockIdx.z;

    // loader mapping: 128 rows x 64 halves; each thread stages one row-half (32 vals)
    const int row  = tid >> 1;
    const int colh = (tid & 1) * 32;

    // warp tile origin: 2 warp-rows x 4 warp-cols
    const int wm = (wid >> 2) * 64;
    const int wn = (wid & 3) * 32;

    // source row pointers (fixed per thread)
    float g = 1.0f;
    const float* aRow;
    const float* bRow;
    if (GATED) {
        g    = __ldg(gate + (bm + row) * E_DIM + z);
        aRow = A + (size_t)(bm + row) * 512;
        bRow = Bm + ((size_t)z * 512 + (bn + row)) * 512;
    } else {
        aRow = A + (size_t)(bm + row) * K + z * NCHUNK * KCH;
        bRow = Bm + (size_t)(bn + row) * K + z * NCHUNK * KCH;
    }

    // ldmatrix base addresses (constant per thread; += ks*32 bytes per k-step)
    // A m-tile i: rows wm+16i+(lane%16), 16B-half (lane/16)
    uint32_t aAddr[4];
#pragma unroll
    for (int i = 0; i < 4; ++i)
        aAddr[i] = smem_u32(&As[wm + 16 * i + (lane & 15)][0]) + (lane >> 4) * 16;
    // B n-tile pair j: rows wn+16j+(lane%8)+((lane/16)*8), 16B-half ((lane>>3)&1)
    uint32_t bAddr[2];
#pragma unroll
    for (int j = 0; j < 2; ++j)
        bAddr[j] = smem_u32(&Bs[wn + 16 * j + (lane & 7) + ((lane >> 4) << 3)][0])
                   + ((lane >> 3) & 1) * 16;

    float acc[4][4][4];
#pragma unroll
    for (int i = 0; i < 4; ++i)
#pragma unroll
        for (int j = 0; j < 4; ++j)
#pragma unroll
            for (int q = 0; q < 4; ++q) acc[i][j][q] = 0.0f;

    // staged global-load registers (one chunk of A-row-half + B-row-half)
    float4 va[8], vb[8];

    // NOTE: + colh — each thread loads the k-range it stages (bug fixed R11)
    auto loadChunk = [&](int c) {
        const float4* ap = (const float4*)(aRow + c * KCH + colh);
        const float4* bp = (const float4*)(bRow + c * KCH + colh);
#pragma unroll
        for (int q = 0; q < 8; ++q) va[q] = __ldg(ap + q);
#pragma unroll
        for (int q = 0; q < 8; ++q) vb[q] = __ldg(bp + q);
    };

    // convert regs -> fp16 smem at S[row][colh..colh+31]
    auto storeHalf = [&](const float4* v, __half (*S)[ASTR], float scale) {
#pragma unroll
        for (int q = 0; q < 4; ++q) {
            __half2 h0 = __floats2half2_rn(v[2*q].x * scale,   v[2*q].y * scale);
            __half2 h1 = __floats2half2_rn(v[2*q].z * scale,   v[2*q].w * scale);
            __half2 h2 = __floats2half2_rn(v[2*q+1].x * scale, v[2*q+1].y * scale);
            __half2 h3 = __floats2half2_rn(v[2*q+1].z * scale, v[2*q+1].w * scale);
            uint4 u;
            u.x = *(uint32_t*)&h0; u.y = *(uint32_t*)&h1;
            u.z = *(uint32_t*)&h2; u.w = *(uint32_t*)&h3;
            *(uint4*)&S[row][colh + 8 * q] = u;   // row*144 + colh*2 + 16q : 16B aligned
        }
    };

    loadChunk(0);

#pragma unroll 1
    for (int c = 0; c < NCHUNK; ++c) {
        storeHalf(va, As, GATED ? g : 1.0f);
        storeHalf(vb, Bs, 1.0f);
        __syncthreads();

        // prefetch next chunk's globals while MMA runs on this chunk's smem
        if (c + 1 < NCHUNK) loadChunk(c + 1);

#pragma unroll
        for (int ks = 0; ks < 4; ++ks) {        // 4 x k16 per 64-chunk
            uint32_t a[4][4], b[2][4];
#pragma unroll
            for (int i = 0; i < 4; ++i)
                ldm_x4(a[i][0], a[i][1], a[i][2], a[i][3], aAddr[i] + ks * 32);
#pragma unroll
            for (int j = 0; j < 2; ++j)
                ldm_x4(b[j][0], b[j][1], b[j][2], b[j][3], bAddr[j] + ks * 32);
#pragma unroll
            for (int i = 0; i < 4; ++i) {
#pragma unroll
                for (int j = 0; j < 2; ++j) {
                    mma16816(acc[i][2*j],     a[i][0], a[i][1], a[i][2], a[i][3],
                             b[j][0], b[j][1]);
                    mma16816(acc[i][2*j + 1], a[i][0], a[i][1], a[i][2], a[i][3],
                             b[j][2], b[j][3]);
                }
            }
        }
        __syncthreads();
    }

    // epilogue: c-frag lane mapping -> P[z]
    float* Cp = P + ((size_t)z << 18);
    const int er = lane >> 2;         // 0..7
    const int ec = (lane & 3) * 2;
#pragma unroll
    for (int i = 0; i < 4; ++i) {
#pragma unroll
        for (int j = 0; j < 4; ++j) {
            const int r0 = bm + wm + 16 * i + er;
            const int cc = bn + wn + 8 * j + ec;
            *(float2*)(Cp + (size_t)r0 * H_DIM + cc)
                = make_float2(acc[i][j][0], acc[i][j][1]);
            *(float2*)(Cp + (size_t)(r0 + 8) * H_DIM + cc)
                = make_float2(acc[i][j][2], acc[i][j][3]);
        }
    }
}

// ----------------------------------------------------------------------
// combine SPLITK partials + broadcast bias (+ optional elu):  gating layers
// ----------------------------------------------------------------------
__global__ __launch_bounds__(256)
void combine_bias(const float* __restrict__ P, const float* __restrict__ bias,
                  float* __restrict__ out, int do_elu)
{
    const int base = (blockIdx.x * blockDim.x + threadIdx.x) * 2;
    const int n = base & (H_DIM - 1);
    float2 s = *(const float2*)(P + base);
#pragma unroll
    for (int zz = 1; zz < SPLITK; ++zz) {
        float2 p = *(const float2*)(P + (size_t)zz * B_DIM * H_DIM + base);
        s.x += p.x; s.y += p.y;
    }
    float2 bv = *(const float2*)(bias + n);
    float v0 = s.x + bv.x, v1 = s.y + bv.y;
    if (do_elu) { v0 = elu_f(v0); v1 = elu_f(v1); }
    *(float2*)(out + base) = make_float2(v0, v1);
}

// ----------------------------------------------------------------------
// combine SPLITK partials + blended expert bias (+ optional elu):  MoE layers
// ----------------------------------------------------------------------
__global__ __launch_bounds__(256)
void combine_moe(const float* __restrict__ P, const float* __restrict__ gate,
                 const float* __restrict__ beta, float* __restrict__ out, int do_elu)
{
    const int base = (blockIdx.x * blockDim.x + threadIdx.x) * 2;
    const int m = base >> 9;
    const int n = base & 511;
    float2 s = *(const float2*)(P + base);
#pragma unroll
    for (int zz = 1; zz < SPLITK; ++zz) {
        float2 p = *(const float2*)(P + (size_t)zz * B_DIM * H_DIM + base);
        s.x += p.x; s.y += p.y;
    }
#pragma unroll
    for (int e = 0; e < E_DIM; ++e) {
        const float ge = __ldg(gate + m * E_DIM + e);
        const float2 bb = *(const float2*)(beta + e * H_DIM + n);
        s.x = fmaf(ge, bb.x, s.x);
        s.y = fmaf(ge, bb.y, s.y);
    }
    float v0 = s.x, v1 = s.y;
    if (do_elu) { v0 = elu_f(v0); v1 = elu_f(v1); }
    *(float2*)(out + base) = make_float2(v0, v1);
}

// ----------------------------------------------------------------------
// final gating layer: logits = G1 @ gw2^T + gb2 (N=8, K=512), row softmax
// ----------------------------------------------------------------------
__global__ __launch_bounds__(256)
void gating_softmax(const float* __restrict__ G, const float* __restrict__ W,
                    const float* __restrict__ bias, float* __restrict__ gate)
{
    const int warp = (blockIdx.x * blockDim.x + threadIdx.x) >> 5;
    const int lane = threadIdx.x & 31;
    if (warp >= B_DIM) return;

    float acc[E_DIM] = {0, 0, 0, 0, 0, 0, 0, 0};
    const float* grow = G + (size_t)warp * H_DIM;
    for (int k = lane; k < H_DIM; k += 32) {
        const float xv = grow[k];
#pragma unroll
        for (int e = 0; e < E_DIM; ++e)
            acc[e] = fmaf(xv, __ldg(W + e * H_DIM + k), acc[e]);
    }
#pragma unroll
    for (int e = 0; e < E_DIM; ++e) {
#pragma unroll
        for (int off = 16; off > 0; off >>= 1)
            acc[e] += __shfl_xor_sync(0xffffffffu, acc[e], off);
    }
    if (lane == 0) {
        float v[E_DIM], mx = -1e30f;
#pragma unroll
        for (int e = 0; e < E_DIM; ++e) {
            v[e] = acc[e] + __ldg(bias + e);
            mx = fmaxf(mx, v[e]);
        }
        float s = 0.f;
#pragma unroll
        for (int e = 0; e < E_DIM; ++e) { v[e] = expf(v[e] - mx); s += v[e]; }
        const float inv = 1.0f / s;
#pragma unroll
        for (int e = 0; e < E_DIM; ++e)
            gate[warp * E_DIM + e] = v[e] * inv;
    }
}

// ----------------------------------------------------------------------
extern "C" void kernel_launch(void* const* d_in, const int* in_sizes, int n_in,
                              void* d_out, int out_size)
{
    const float* x      = (const float*)d_in[0];
    const float* gw0    = (const float*)d_in[1];
    const float* gb0    = (const float*)d_in[2];
    const float* gw1    = (const float*)d_in[3];
    const float* gb1    = (const float*)d_in[4];
    const float* gw2    = (const float*)d_in[5];
    const float* gb2    = (const float*)d_in[6];
    const float* alpha0 = (const float*)d_in[7];
    const float* beta0  = (const float*)d_in[8];
    const float* alpha1 = (const float*)d_in[9];
    const float* beta1  = (const float*)d_in[10];
    const float* alpha2 = (const float*)d_in[11];
    const float* beta2  = (const float*)d_in[12];
    float* out = (float*)d_out;

    float *P, *G0, *G1, *gate, *H1, *H2;
    cudaGetSymbolAddress((void**)&P,    d_P);
    cudaGetSymbolAddress((void**)&G0,   d_G0);
    cudaGetSymbolAddress((void**)&G1,   d_G1);
    cudaGetSymbolAddress((void**)&gate, d_gate);
    cudaGetSymbolAddress((void**)&H1,   d_H1);
    cudaGetSymbolAddress((void**)&H2,   d_H2);

    const dim3 gg(B_DIM / TILE_M, H_DIM / TILE_N, SPLITK);  // 4 x 4 x 8 = 128 CTAs
    const int cgrid = (B_DIM * H_DIM / 2) / 256;            // 512 blocks

    // gating MLP (K=512 -> 64 per z -> 1 chunk)
    hmma_gemm<0, 1><<<gg, NTHREADS>>>(x,  gw0, nullptr, P, F_DIM);
    combine_bias<<<cgrid, 256>>>(P, gb0, G0, 1);
    hmma_gemm<0, 1><<<gg, NTHREADS>>>(G0, gw1, nullptr, P, H_DIM);
    combine_bias<<<cgrid, 256>>>(P, gb1, G1, 1);
    gating_softmax<<<(B_DIM * 32) / 256, 256>>>(G1, gw2, gb2, gate);

    // expert layers (K = E*512 = 4096 -> one expert per z -> 8 chunks)
    hmma_gemm<1, 8><<<gg, NTHREADS>>>(x,  alpha0, gate, P, E_DIM * F_DIM);
    combine_moe<<<cgrid, 256>>>(P, gate, beta0, H1, 1);
    hmma_gemm<1, 8><<<gg, NTHREADS>>>(H1, alpha1, gate, P, E_DIM * H_DIM);
    combine_moe<<<cgrid, 256>>>(P, gate, beta1, H2, 1);
    hmma_gemm<1, 8><<<gg, NTHREADS>>>(H2, alpha2, gate, P, E_DIM * H_DIM);
    combine_moe<<<cgrid, 256>>>(P, gate, beta2, out, 0);
}

// round 15
// speedup vs baseline: 2.6877x; 1.8123x over previous
#include <cuda_runtime.h>
#include <cuda_fp16.h>
#include <cstdint>
#include <cstddef>
#include <math.h>

// Problem constants (fixed by the dataset)
#define B_DIM 512
#define F_DIM 512
#define H_DIM 512
#define E_DIM 8
#define SPLITK 8

#define NTHREADS 256
#define TILE_M 128
#define TILE_N 128
#define KCH 32            // fp16 k-elements staged per chunk (double-buffered)
#define ASTR 40           // smem row stride in halves (80B = 20 words; 20r mod 32 distinct -> conflict-free ldmatrix)

// -------- scratch (no allocations allowed; __device__ globals) --------
__device__ float d_P[SPLITK * B_DIM * H_DIM];   // split-K partials
__device__ float d_G0[B_DIM * H_DIM];
__device__ float d_G1[B_DIM * H_DIM];
__device__ float d_gate[B_DIM * E_DIM];
__device__ float d_H1[B_DIM * H_DIM];
__device__ float d_H2[B_DIM * H_DIM];

__device__ __forceinline__ float elu_f(float x) { return x > 0.0f ? x : expm1f(x); }

__device__ __forceinline__ uint32_t smem_u32(const void* p) {
    uint32_t a;
    asm("{ .reg .u64 t; cvta.to.shared.u64 t, %1; cvt.u32.u64 %0, t; }"
        : "=r"(a) : "l"(p));
    return a;
}

// ldmatrix x4: four 8x8 b16 matrices (sm_75+, no arch suffix needed)
__device__ __forceinline__ void ldm_x4(uint32_t& r0, uint32_t& r1,
                                       uint32_t& r2, uint32_t& r3, uint32_t addr) {
    asm volatile("ldmatrix.sync.aligned.m8n8.x4.shared.b16 {%0,%1,%2,%3}, [%4];"
                 : "=r"(r0), "=r"(r1), "=r"(r2), "=r"(r3) : "r"(addr));
}

// warp-level HMMA: m16n8k16, fp16 in, fp32 accumulate (sm_80+)
__device__ __forceinline__ void mma16816(float* c,
                                         uint32_t a0, uint32_t a1, uint32_t a2, uint32_t a3,
                                         uint32_t b0, uint32_t b1) {
    asm volatile(
        "mma.sync.aligned.m16n8k16.row.col.f32.f16.f16.f32 "
        "{%0,%1,%2,%3}, {%4,%5,%6,%7}, {%8,%9}, {%0,%1,%2,%3};"
        : "+f"(c[0]), "+f"(c[1]), "+f"(c[2]), "+f"(c[3])
        : "r"(a0), "r"(a1), "r"(a2), "r"(a3), "r"(b0), "r"(b1));
}

// ----------------------------------------------------------------------
// hmma_gemm: split-K partial of C = A' @ B'^T (fp16 tensor cores, fp32 acc)
//   GATED==0: A'(m,k)=A[m*K+k], B'(n,k)=Bm[n*K+k];  k-window [z*NCHUNK*KCH,...)
//   GATED==1: K = E*512; each z-slice is exactly one expert (e == z):
//             A'(m,k)=gate[m,z]*A[m*512+f], B'(n,k)=alpha[(z*512+n)*512+f]
// Grid (4,4,SPLITK); CTA tile 128x128; 8 warps, warp tile 64x32.
// DOUBLE-BUFFERED pipeline, one __syncthreads per chunk:
//   loadChunk(c+1) -> MMA on buf(c) -> store regs to buf(c+1) -> sync
// ----------------------------------------------------------------------
template <int GATED, int NCHUNK>
__global__ __launch_bounds__(NTHREADS)
void hmma_gemm(const float* __restrict__ A, const float* __restrict__ Bm,
               const float* __restrict__ gate, float* __restrict__ P, int K)
{
    __shared__ __align__(16) __half As[2][TILE_M][ASTR];
    __shared__ __align__(16) __half Bs[2][TILE_N][ASTR];
    const uint32_t BUFB = (uint32_t)(TILE_M * ASTR * 2);   // byte stride between buffers

    const int tid  = threadIdx.x;
    const int wid  = tid >> 5;
    const int lane = tid & 31;
    const int bm = blockIdx.x * TILE_M;
    const int bn = blockIdx.y * TILE_N;
    const int z  = blockIdx.z;

    // loader mapping: 128 rows x 32 halves; each thread stages one row-half (16 vals)
    const int row  = tid >> 1;
    const int colh = (tid & 1) * 16;

    // warp tile origin: 2 warp-rows x 4 warp-cols
    const int wm = (wid >> 2) * 64;
    const int wn = (wid & 3) * 32;

    // source row pointers (fixed per thread)
    float g = 1.0f;
    const float* aRow;
    const float* bRow;
    if (GATED) {
        g    = __ldg(gate + (bm + row) * E_DIM + z);
        aRow = A + (size_t)(bm + row) * 512;
        bRow = Bm + ((size_t)z * 512 + (bn + row)) * 512;
    } else {
        aRow = A + (size_t)(bm + row) * K + z * NCHUNK * KCH;
        bRow = Bm + (size_t)(bn + row) * K + z * NCHUNK * KCH;
    }

    // ldmatrix base addresses into buffer 0 (+ BUFB for buffer 1; + ks*32B per k-step)
    uint32_t aAddr[4];
#pragma unroll
    for (int i = 0; i < 4; ++i)
        aAddr[i] = smem_u32(&As[0][wm + 16 * i + (lane & 15)][0]) + (lane >> 4) * 16;
    uint32_t bAddr[2];
#pragma unroll
    for (int j = 0; j < 2; ++j)
        bAddr[j] = smem_u32(&Bs[0][wn + 16 * j + (lane & 7) + ((lane >> 4) << 3)][0])
                   + ((lane >> 3) & 1) * 16;

    float acc[4][4][4];
#pragma unroll
    for (int i = 0; i < 4; ++i)
#pragma unroll
        for (int j = 0; j < 4; ++j)
#pragma unroll
            for (int q = 0; q < 4; ++q) acc[i][j][q] = 0.0f;

    // staged global-load registers (one chunk of A-row-half + B-row-half)
    float4 va[4], vb[4];

    auto loadChunk = [&](int c) {
        const float4* ap = (const float4*)(aRow + c * KCH + colh);
        const float4* bp = (const float4*)(bRow + c * KCH + colh);
#pragma unroll
        for (int q = 0; q < 4; ++q) va[q] = __ldg(ap + q);
#pragma unroll
        for (int q = 0; q < 4; ++q) vb[q] = __ldg(bp + q);
    };

    // convert 16 fp32 regs -> fp16 smem at S[buf][row][colh..colh+15]
    auto storeHalf = [&](const float4* v, __half (*S)[ASTR], float scale) {
#pragma unroll
        for (int q = 0; q < 2; ++q) {
            __half2 h0 = __floats2half2_rn(v[2*q].x * scale,   v[2*q].y * scale);
            __half2 h1 = __floats2half2_rn(v[2*q].z * scale,   v[2*q].w * scale);
            __half2 h2 = __floats2half2_rn(v[2*q+1].x * scale, v[2*q+1].y * scale);
            __half2 h3 = __floats2half2_rn(v[2*q+1].z * scale, v[2*q+1].w * scale);
            uint4 u;
            u.x = *(uint32_t*)&h0; u.y = *(uint32_t*)&h1;
            u.z = *(uint32_t*)&h2; u.w = *(uint32_t*)&h3;
            *(uint4*)&S[row][colh + 8 * q] = u;   // row*80 + colh*2 + 16q : 16B aligned
        }
    };

    // prologue: fill buffer 0
    loadChunk(0);
    storeHalf(va, As[0], GATED ? g : 1.0f);
    storeHalf(vb, Bs[0], 1.0f);
    __syncthreads();

#pragma unroll 1
    for (int c = 0; c < NCHUNK; ++c) {
        const uint32_t bo = (c & 1) ? BUFB : 0;
        const bool more = (c + 1) < NCHUNK;
        if (more) loadChunk(c + 1);     // LDGs overlap the MMA phase below

#pragma unroll
        for (int ks = 0; ks < 2; ++ks) {        // 2 x k16 per 32-chunk
            uint32_t a[4][4], b[2][4];
#pragma unroll
            for (int i = 0; i < 4; ++i)
                ldm_x4(a[i][0], a[i][1], a[i][2], a[i][3], aAddr[i] + bo + ks * 32);
#pragma unroll
            for (int j = 0; j < 2; ++j)
                ldm_x4(b[j][0], b[j][1], b[j][2], b[j][3], bAddr[j] + bo + ks * 32);
#pragma unroll
            for (int i = 0; i < 4; ++i) {
#pragma unroll
                for (int j = 0; j < 2; ++j) {
                    mma16816(acc[i][2*j],     a[i][0], a[i][1], a[i][2], a[i][3],
                             b[j][0], b[j][1]);
                    mma16816(acc[i][2*j + 1], a[i][0], a[i][1], a[i][2], a[i][3],
                             b[j][2], b[j][3]);
                }
            }
        }

        if (more) {                      // stage into the *other* buffer (no hazard)
            __half (*Sa)[ASTR] = (c & 1) ? As[0] : As[1];
            __half (*Sb)[ASTR] = (c & 1) ? Bs[0] : Bs[1];
            storeHalf(va, Sa, GATED ? g : 1.0f);
            storeHalf(vb, Sb, 1.0f);
        }
        __syncthreads();                 // orders both buffer handoffs
    }

    // epilogue: c-frag lane mapping -> P[z]
    float* Cp = P + ((size_t)z << 18);
    const int er = lane >> 2;         // 0..7
    const int ec = (lane & 3) * 2;
#pragma unroll
    for (int i = 0; i < 4; ++i) {
#pragma unroll
        for (int j = 0; j < 4; ++j) {
            const int r0 = bm + wm + 16 * i + er;
            const int cc = bn + wn + 8 * j + ec;
            *(float2*)(Cp + (size_t)r0 * H_DIM + cc)
                = make_float2(acc[i][j][0], acc[i][j][1]);
            *(float2*)(Cp + (size_t)(r0 + 8) * H_DIM + cc)
                = make_float2(acc[i][j][2], acc[i][j][3]);
        }
    }
}

// ----------------------------------------------------------------------
// combine SPLITK partials + broadcast bias (+ optional elu):  gating layers
// ----------------------------------------------------------------------
__global__ __launch_bounds__(256)
void combine_bias(const float* __restrict__ P, const float* __restrict__ bias,
                  float* __restrict__ out, int do_elu)
{
    const int base = (blockIdx.x * blockDim.x + threadIdx.x) * 2;
    const int n = base & (H_DIM - 1);
    float2 s = *(const float2*)(P + base);
#pragma unroll
    for (int zz = 1; zz < SPLITK; ++zz) {
        float2 p = *(const float2*)(P + (size_t)zz * B_DIM * H_DIM + base);
        s.x += p.x; s.y += p.y;
    }
    float2 bv = *(const float2*)(bias + n);
    float v0 = s.x + bv.x, v1 = s.y + bv.y;
    if (do_elu) { v0 = elu_f(v0); v1 = elu_f(v1); }
    *(float2*)(out + base) = make_float2(v0, v1);
}

// ----------------------------------------------------------------------
// combine SPLITK partials + blended expert bias (+ optional elu):  MoE layers
// ----------------------------------------------------------------------
__global__ __launch_bounds__(256)
void combine_moe(const float* __restrict__ P, const float* __restrict__ gate,
                 const float* __restrict__ beta, float* __restrict__ out, int do_elu)
{
    const int base = (blockIdx.x * blockDim.x + threadIdx.x) * 2;
    const int m = base >> 9;
    const int n = base & 511;
    float2 s = *(const float2*)(P + base);
#pragma unroll
    for (int zz = 1; zz < SPLITK; ++zz) {
        float2 p = *(const float2*)(P + (size_t)zz * B_DIM * H_DIM + base);
        s.x += p.x; s.y += p.y;
    }
#pragma unroll
    for (int e = 0; e < E_DIM; ++e) {
        const float ge = __ldg(gate + m * E_DIM + e);
        const float2 bb = *(const float2*)(beta + e * H_DIM + n);
        s.x = fmaf(ge, bb.x, s.x);
        s.y = fmaf(ge, bb.y, s.y);
    }
    float v0 = s.x, v1 = s.y;
    if (do_elu) { v0 = elu_f(v0); v1 = elu_f(v1); }
    *(float2*)(out + base) = make_float2(v0, v1);
}

// ----------------------------------------------------------------------
// final gating layer: logits = G1 @ gw2^T + gb2 (N=8, K=512), row softmax
// ----------------------------------------------------------------------
__global__ __launch_bounds__(256)
void gating_softmax(const float* __restrict__ G, const float* __restrict__ W,
                    const float* __restrict__ bias, float* __restrict__ gate)
{
    const int warp = (blockIdx.x * blockDim.x + threadIdx.x) >> 5;
    const int lane = threadIdx.x & 31;
    if (warp >= B_DIM) return;

    float acc[E_DIM] = {0, 0, 0, 0, 0, 0, 0, 0};
    const float* grow = G + (size_t)warp * H_DIM;
    for (int k = lane; k < H_DIM; k += 32) {
        const float xv = grow[k];
#pragma unroll
        for (int e = 0; e < E_DIM; ++e)
            acc[e] = fmaf(xv, __ldg(W + e * H_DIM + k), acc[e]);
    }
#pragma unroll
    for (int e = 0; e < E_DIM; ++e) {
#pragma unroll
        for (int off = 16; off > 0; off >>= 1)
            acc[e] += __shfl_xor_sync(0xffffffffu, acc[e], off);
    }
    if (lane == 0) {
        float v[E_DIM], mx = -1e30f;
#pragma unroll
        for (int e = 0; e < E_DIM; ++e) {
            v[e] = acc[e] + __ldg(bias + e);
            mx = fmaxf(mx, v[e]);
        }
        float s = 0.f;
#pragma unroll
        for (int e = 0; e < E_DIM; ++e) { v[e] = expf(v[e] - mx); s += v[e]; }
        const float inv = 1.0f / s;
#pragma unroll
        for (int e = 0; e < E_DIM; ++e)
            gate[warp * E_DIM + e] = v[e] * inv;
    }
}

// ----------------------------------------------------------------------
extern "C" void kernel_launch(void* const* d_in, const int* in_sizes, int n_in,
                              void* d_out, int out_size)
{
    const float* x      = (const float*)d_in[0];
    const float* gw0    = (const float*)d_in[1];
    const float* gb0    = (const float*)d_in[2];
    const float* gw1    = (const float*)d_in[3];
    const float* gb1    = (const float*)d_in[4];
    const float* gw2    = (const float*)d_in[5];
    const float* gb2    = (const float*)d_in[6];
    const float* alpha0 = (const float*)d_in[7];
    const float* beta0  = (const float*)d_in[8];
    const float* alpha1 = (const float*)d_in[9];
    const float* beta1  = (const float*)d_in[10];
    const float* alpha2 = (const float*)d_in[11];
    const float* beta2  = (const float*)d_in[12];
    float* out = (float*)d_out;

    float *P, *G0, *G1, *gate, *H1, *H2;
    cudaGetSymbolAddress((void**)&P,    d_P);
    cudaGetSymbolAddress((void**)&G0,   d_G0);
    cudaGetSymbolAddress((void**)&G1,   d_G1);
    cudaGetSymbolAddress((void**)&gate, d_gate);
    cudaGetSymbolAddress((void**)&H1,   d_H1);
    cudaGetSymbolAddress((void**)&H2,   d_H2);

    const dim3 gg(B_DIM / TILE_M, H_DIM / TILE_N, SPLITK);  // 4 x 4 x 8 = 128 CTAs
    const int cgrid = (B_DIM * H_DIM / 2) / 256;            // 512 blocks

    // k-chunks per split: gating (512/8)/32 = 2; expert (4096/8)/32 = 16
    constexpr int NC_GATE   = (F_DIM / SPLITK) / KCH;          // 2
    constexpr int NC_EXPERT = (E_DIM * F_DIM / SPLITK) / KCH;  // 16

    // gating MLP
    hmma_gemm<0, NC_GATE><<<gg, NTHREADS>>>(x,  gw0, nullptr, P, F_DIM);
    combine_bias<<<cgrid, 256>>>(P, gb0, G0, 1);
    hmma_gemm<0, NC_GATE><<<gg, NTHREADS>>>(G0, gw1, nullptr, P, H_DIM);
    combine_bias<<<cgrid, 256>>>(P, gb1, G1, 1);
    gating_softmax<<<(B_DIM * 32) / 256, 256>>>(G1, gw2, gb2, gate);

    // expert layers (K = E*512 = 4096 -> one expert per z -> 16 chunks)
    hmma_gemm<1, NC_EXPERT><<<gg, NTHREADS>>>(x,  alpha0, gate, P, E_DIM * F_DIM);
    combine_moe<<<cgrid, 256>>>(P, gate, beta0, H1, 1);
    hmma_gemm<1, NC_EXPERT><<<gg, NTHREADS>>>(H1, alpha1, gate, P, E_DIM * H_DIM);
    combine_moe<<<cgrid, 256>>>(P, gate, beta1, H2, 1);
    hmma_gemm<1, NC_EXPERT><<<gg, NTHREADS>>>(H2, alpha2, gate, P, E_DIM * H_DIM);
    combine_moe<<<cgrid, 256>>>(P, gate, beta2, out, 0);
}